// round 15
// baseline (speedup 1.0000x reference)
#include <cuda_runtime.h>
#include <math.h>
#include <stdint.h>

#define NEG_SLOPE 0.2f
#define KNN_K 20
#define BATCH 8
#define NPTS 2048
#define CO 64
#define CIN 6
#define ROWS 384
#define NPOINTS (BATCH * NPTS)

__device__ int g_knn[NPOINTS * KNN_K];

typedef unsigned long long u64;

__device__ __forceinline__ void ffma2(u64& d, u64 a, u64 b) {
    asm("fma.rn.f32x2 %0, %1, %2, %0;" : "+l"(d) : "l"(a), "l"(b));
}
__device__ __forceinline__ u64 dup2(float w) {
    u64 r; asm("mov.b64 %0, {%1, %1};" : "=l"(r) : "f"(w)); return r;
}
__device__ __forceinline__ u64 pack2(float lo, float hi) {
    u64 r; asm("mov.b64 %0, {%1, %2};" : "=l"(r) : "f"(lo), "f"(hi)); return r;
}
__device__ __forceinline__ void unpack2(float& lo, float& hi, u64 v) {
    asm("mov.b64 {%0, %1}, %2;" : "=f"(lo), "=f"(hi) : "l"(v));
}

// ===========================================================================
// Kernel 1: KNN v2 — adaptive-threshold collect.
// 512 blocks x 256 threads; 32 points/block, 8 lanes/point (same warp).
// tau = min over lanes of lane-exact-top-3rd  (valid lower bound on the true
// 20th by pigeonhole: 8*3 = 24 > 20). Warmup 16 j/lane builds chains -> tau;
// full scan inserts d >= tau into smem buffer; exact (d desc, j asc) top-20
// by rank-select. Overflow (never expected, cap=128 ~11 sigma) -> exact
// serial fallback chain.
// ===========================================================================
#define KNN_THR 256
#define KNN_PPB 32
#define KSEGLEN 256
#define KCAP 128
#define KWARM 16

#define KOFF_P     0                               // float4[2048] = 8192 fl
#define KOFF_BD    (NPTS * 4)                      // [32][128] = 4096
#define KOFF_BJ    (KOFF_BD + KNN_PPB * KCAP)      // [32][128] = 4096 (int)
#define KOFF_TH    (KOFF_BJ + KNN_PPB * KCAP)      // [32][8] thirds = 256
#define KOFF_TAU   (KOFF_TH + KNN_PPB * 8)         // 32
#define KOFF_CNT   (KOFF_TAU + KNN_PPB)            // 32 (int)
#define KOFF_FLG   (KOFF_CNT + KNN_PPB)            // 32 (int)
#define KNN_SMEM_FLOATS (KOFF_FLG + KNN_PPB)
#define KNN_SMEM_BYTES (KNN_SMEM_FLOATS * 4)

__global__ __launch_bounds__(KNN_THR) void knn_kernel(const float* __restrict__ x) {
    extern __shared__ float ksm[];
    float4* sP    = (float4*)(ksm + KOFF_P);
    float*  bufD  = ksm + KOFF_BD;
    int*    bufJ  = (int*)(ksm + KOFF_BJ);
    float*  sTh   = ksm + KOFF_TH;
    volatile float* sTau = ksm + KOFF_TAU;
    int*    sCnt  = (int*)(ksm + KOFF_CNT);
    int*    sFlg  = (int*)(ksm + KOFF_FLG);

    const int b = blockIdx.x >> 6;          // 64 blocks per batch
    const int chunk = blockIdx.x & 63;      // 32-point chunk
    const float* xb = x + (size_t)b * 3 * NPTS;

    const int t = threadIdx.x;
    for (int j = t; j < NPTS; j += KNN_THR) {
        float a0 = xb[j], a1 = xb[NPTS + j], a2 = xb[2 * NPTS + j];
        float xx = (a0 * a0 + a1 * a1) + a2 * a2;
        sP[j] = make_float4(a0, a1, a2, xx);
    }
    if (t < KNN_PPB) { sCnt[t] = 0; sFlg[t] = 0; }
    __syncthreads();

    const int pp = t >> 3;          // point in block
    const int s  = t & 7;           // lane segment
    const int i  = (chunk << 5) + pp;

    float4 cv = sP[i];
    const float c0 = cv.x, c1 = cv.y, c2 = cv.z, cxx = cv.w;

    const int j0 = s * KSEGLEN;

    // ---- top-3 chain state ----
    float t0 = -INFINITY, t1 = -INFINITY, t2 = -INFINITY;

    // ---- warmup: build chains over first KWARM j of the segment ----
#pragma unroll 4
    for (int jj = 0; jj < KWARM; jj++) {
        int j = j0 + jj;
        float4 p4 = sP[j];
        float d = c0 * p4.x;
        d = fmaf(c1, p4.y, d);
        d = fmaf(c2, p4.z, d);
        d = 2.0f * d - cxx - p4.w;
        if (d > t2) {
            float m0 = fmaxf(t0, d); d = fminf(t0, d); t0 = m0;
            float m1 = fmaxf(t1, d); d = fminf(t1, d); t1 = m1;
            t2 = fmaxf(t2, d);
        }
    }
    sTh[pp * 8 + s] = t2;
    __syncwarp();
    if (s == 0) {
        float m = sTh[pp * 8];
#pragma unroll
        for (int q = 1; q < 8; q++) m = fminf(m, sTh[pp * 8 + q]);
        sTau[pp] = m;
    }
    __syncwarp();
    float rtau = sTau[pp];

    // ---- insert-only pass over the warmup range (chains already have them)
#pragma unroll 4
    for (int jj = 0; jj < KWARM; jj++) {
        int j = j0 + jj;
        float4 p4 = sP[j];
        float d = c0 * p4.x;
        d = fmaf(c1, p4.y, d);
        d = fmaf(c2, p4.z, d);
        d = 2.0f * d - cxx - p4.w;
        if (d >= rtau) {
            int pos = atomicAdd(&sCnt[pp], 1);
            if (pos < KCAP) { bufD[pp * KCAP + pos] = d; bufJ[pp * KCAP + pos] = j; }
            else sFlg[pp] = 1;
        }
    }

    // ---- main scan: chain update + threshold insert ----
#pragma unroll 2
    for (int jj = KWARM; jj < KSEGLEN; jj++) {
        int j = j0 + jj;
        float4 p4 = sP[j];
        float d = c0 * p4.x;
        d = fmaf(c1, p4.y, d);
        d = fmaf(c2, p4.z, d);
        d = 2.0f * d - cxx - p4.w;
        if (d > t2) {
            float dd = d;
            float m0 = fmaxf(t0, dd); dd = fminf(t0, dd); t0 = m0;
            float m1 = fmaxf(t1, dd); dd = fminf(t1, dd); t1 = m1;
            t2 = fmaxf(t2, dd);
            sTh[pp * 8 + s] = t2;
        }
        if (d >= rtau) {
            int pos = atomicAdd(&sCnt[pp], 1);
            if (pos < KCAP) { bufD[pp * KCAP + pos] = d; bufJ[pp * KCAP + pos] = j; }
            else sFlg[pp] = 1;
        }
        if ((jj & 7) == 7) {
            if (s == 0) {
                float m = sTh[pp * 8];
#pragma unroll
                for (int q = 1; q < 8; q++) m = fminf(m, sTh[pp * 8 + q]);
                sTau[pp] = m;
            }
            rtau = sTau[pp];   // stale-safe: tau only increases
        }
    }
    __syncwarp();

    // ---- selection ----
    int cnt = sCnt[pp];
    if (cnt > KCAP) cnt = KCAP;
    int* outp20 = g_knn + ((size_t)b * NPTS + i) * KNN_K;

    if (sFlg[pp] == 0) {
        // rank-select exact top-20 by (d desc, j asc)
        const float* cd = bufD + pp * KCAP;
        const int*   cj = bufJ + pp * KCAP;
        for (int q = s; q < cnt; q += 8) {
            float d = cd[q]; int j = cj[q];
            int rank = 0;
            for (int q2 = 0; q2 < cnt; q2++) {
                float d2 = cd[q2]; int j2 = cj[q2];
                rank += ((d2 > d) || (d2 == d && j2 < j)) ? 1 : 0;
            }
            if (rank < KNN_K) outp20[rank] = j;
        }
    } else if (s == 0) {
        // exact serial fallback (never expected)
        float bd[KNN_K]; int bi[KNN_K];
#pragma unroll
        for (int k = 0; k < KNN_K; k++) { bd[k] = -INFINITY; bi[k] = 0; }
        for (int j = 0; j < NPTS; j++) {
            float4 p4 = sP[j];
            float d = c0 * p4.x;
            d = fmaf(c1, p4.y, d);
            d = fmaf(c2, p4.z, d);
            d = 2.0f * d - cxx - p4.w;
            if (d > bd[KNN_K - 1]) {
                float cdv = d; int civ = j;
#pragma unroll
                for (int k = 0; k < KNN_K; k++) {
                    bool sw = cdv > bd[k];
                    float td = bd[k]; int ti = bi[k];
                    if (sw) { bd[k] = cdv; bi[k] = civ; cdv = td; civ = ti; }
                }
            }
        }
#pragma unroll
        for (int k = 0; k < KNN_K; k++) outp20[k] = bi[k];
    }
}

// ===========================================================================
// Kernel 2: PERSISTENT fused edge kernel (148 blocks x 512 threads, PTS=8).
// (unchanged from R14 — whole-k single p-pass, 40 u64 G-accumulators)
// ===========================================================================
#define PTS 8
#define THR 512
#define NTILES ((NPOINTS + PTS - 1) / PTS)   // 2048
#define EDGE_GRID 148

#define EPAD 9
#define YROW 24

#define F_WQ   0
#define F_WB   (F_WQ + 16384)
#define F_Y    (F_WB + 8192)
#define F_E    (F_Y + 12288)
#define F_W0   (F_E + 1440)
#define F_B0S  (F_W0 + 384)
#define F_B0B  (F_B0S + 64)
#define F_B1S  (F_B0B + 64)
#define F_B1B  (F_B1S + 64)
#define F_WC   (F_B1B + 64)
#define F_BNC  (F_WC + 192)
#define F_X1   (F_BNC + 8)
#define SMEM_FLOATS (F_X1 + 512)
#define SMEM_BYTES (SMEM_FLOATS * 4)

__global__ __launch_bounds__(THR, 1) void edge_kernel(
    const float* __restrict__ x,
    const float* __restrict__ W0,
    const float* __restrict__ bn0_s, const float* __restrict__ bn0_b,
    const float* __restrict__ W1,
    const float* __restrict__ bn1_s, const float* __restrict__ bn1_b,
    const float* __restrict__ Wc,
    const float* __restrict__ bnc_s, const float* __restrict__ bnc_b,
    float* __restrict__ outp)
{
    extern __shared__ float sm[];
    float* sWq  = sm + F_WQ;
    float* sWb  = sm + F_WB;
    float* sY   = sm + F_Y;
    float* sE   = sm + F_E;
    float* sW0  = sm + F_W0;
    float* sB0s = sm + F_B0S;
    float* sB0b = sm + F_B0B;
    float* sB1s = sm + F_B1S;
    float* sB1b = sm + F_B1B;
    float* sWc  = sm + F_WC;
    float* sBnc = sm + F_BNC;
    float* sX1  = sm + F_X1;

    const int t = threadIdx.x;

    for (int g = t; g < ROWS * CO; g += THR) {
        int q = g >> 6;
        int p = g & 63;
        int oo = q / 6;
        int ii = q - oo * 6;
        float w = W1[g];
        if (ii < 4)       sWq[(p * 64 + oo) * 4 + ii] = w;
        else              sWb[(p * 64 + oo) * 2 + (ii - 4)] = w;
    }
    if (t < 384) sW0[t] = W0[t];
    if (t < 64) {
        sB0s[t] = bn0_s[t]; sB0b[t] = bn0_b[t];
        sB1s[t] = bn1_s[t]; sB1b[t] = bn1_b[t];
    }
    if (t < 192) sWc[t] = Wc[t];
    if (t < 3) { sBnc[t] = bnc_s[t]; sBnc[4 + t] = bnc_b[t]; }

    const int pt_g = t >> 6;
    const int o    = t & 63;

    for (int tile = blockIdx.x; tile < NTILES; tile += EDGE_GRID) {
        __syncthreads();

        if (t < PTS * KNN_K) {
            int pt = t / KNN_K, k = t - pt * KNN_K;
            int gp = tile * PTS + pt;
            float e0 = 0.f, e1 = 0.f, e2 = 0.f, c0 = 0.f, c1 = 0.f, c2 = 0.f;
            if (gp < NPOINTS) {
                int b = gp >> 11, n = gp & (NPTS - 1);
                const float* xb = x + (size_t)b * 3 * NPTS;
                c0 = xb[n]; c1 = xb[NPTS + n]; c2 = xb[2 * NPTS + n];
                int j = g_knn[((size_t)b * NPTS + n) * KNN_K + k];
                e0 = xb[j] - c0;
                e1 = xb[NPTS + j] - c1;
                e2 = xb[2 * NPTS + j] - c2;
            }
            float* e = sE + t * EPAD;
            e[0] = e0; e[1] = e1; e[2] = e2;
            e[3] = c0; e[4] = c1; e[5] = c2;
        }
        __syncthreads();

        for (int v = t; v < PTS * CO * KNN_K; v += THR) {
            int pt = v / (CO * KNN_K);
            int rem = v - pt * (CO * KNN_K);
            int p = rem / KNN_K;
            int k = rem - p * KNN_K;
            const float* e = sE + (pt * KNN_K + k) * EPAD;
            const float* w = sW0 + p * 6;
            float d = e[0] * w[0];
            d = fmaf(e[1], w[1], d);
            d = fmaf(e[2], w[2], d);
            d = fmaf(e[3], w[3], d);
            d = fmaf(e[4], w[4], d);
            d = fmaf(e[5], w[5], d);
            float yv = fmaf(d, sB0s[p], sB0b[p]);
            yv = (yv >= 0.0f) ? yv : NEG_SLOPE * yv;
            int half = k / 10, kk = k - half * 10;
            sY[(pt * CO + p) * YROW + half * 12 + kk] = yv;
        }
        __syncthreads();

        {
            const float* ept = sE + (pt_g * KNN_K) * EPAD;
            const float cc0 = ept[3], cc1 = ept[4], cc2 = ept[5];

            union F4 { float4 v; u64 d[2]; };

            u64 g0[10], g1[10], g2[10], gq[10];
#pragma unroll
            for (int q = 0; q < 10; q++) { g0[q] = 0; g1[q] = 0; g2[q] = 0; gq[q] = 0; }

            const float* yb = sY + (pt_g * CO) * YROW;

#pragma unroll 1
            for (int p = 0; p < CO; p++) {
                float4 wq = *(const float4*)(sWq + (p * 64 + o) * 4);
                float2 wb = *(const float2*)(sWb + (p * 64 + o) * 2);
                float qv = wq.w * cc0;
                qv = fmaf(wb.x, cc1, qv);
                qv = fmaf(wb.y, cc2, qv);
                u64 a0d = dup2(wq.x), a1d = dup2(wq.y), a2d = dup2(wq.z), qd = dup2(qv);

                const float* yrow = yb + p * YROW;
                F4 h0a, h0b, h1a, h1b;
                h0a.v = *(const float4*)(yrow);
                h0b.v = *(const float4*)(yrow + 4);
                u64 y4 = *(const u64*)(yrow + 8);
                h1a.v = *(const float4*)(yrow + 12);
                h1b.v = *(const float4*)(yrow + 16);
                u64 y9 = *(const u64*)(yrow + 20);

                u64 y[10];
                y[0] = h0a.d[0]; y[1] = h0a.d[1]; y[2] = h0b.d[0]; y[3] = h0b.d[1]; y[4] = y4;
                y[5] = h1a.d[0]; y[6] = h1a.d[1]; y[7] = h1b.d[0]; y[8] = h1b.d[1]; y[9] = y9;

#pragma unroll
                for (int q = 0; q < 10; q++) {
                    ffma2(g0[q], y[q], a0d);
                    ffma2(g1[q], y[q], a1d);
                    ffma2(g2[q], y[q], a2d);
                    ffma2(gq[q], y[q], qd);
                }
            }

            float maxv = -INFINITY;
#pragma unroll
            for (int q = 0; q < 10; q++) {
                const float* r0 = ept + (2 * q) * EPAD;
                const float* r1 = r0 + EPAD;
                u64 d0 = pack2(r0[0], r1[0]);
                u64 d1 = pack2(r0[1], r1[1]);
                u64 d2 = pack2(r0[2], r1[2]);
                u64 acc = gq[q];
                ffma2(acc, d0, g0[q]);
                ffma2(acc, d1, g1[q]);
                ffma2(acc, d2, g2[q]);
                float lo, hi;
                unpack2(lo, hi, acc);
                maxv = fmaxf(maxv, lo);
                maxv = fmaxf(maxv, hi);
            }

            float vv = fmaf(maxv, sB1s[o], sB1b[o]);
            vv = (vv >= 0.0f) ? vv : NEG_SLOPE * vv;
            sX1[pt_g * 64 + o] = vv;
        }
        __syncthreads();

        if (t < PTS * 3) {
            int pt = t / 3, c = t - pt * 3;
            int gp = tile * PTS + pt;
            if (gp < NPOINTS) {
                int b = gp >> 11, n = gp & (NPTS - 1);
                const float* x1 = sX1 + pt * 64;
                const float* w = sWc + c * 64;
                float d = 0.0f;
#pragma unroll
                for (int oo = 0; oo < 64; oo++) d = fmaf(x1[oo], w[oo], d);
                float z = fmaf(d, sBnc[c], sBnc[4 + c]);
                z = (z >= 0.0f) ? z : NEG_SLOPE * z;
                outp[((size_t)b * 3 + c) * NPTS + n] = z;
            }
        }
    }
}

// ---------------------------------------------------------------------------
extern "C" void kernel_launch(void* const* d_in, const int* in_sizes, int n_in,
                              void* d_out, int out_size)
{
    const float* x     = (const float*)d_in[0];
    const float* W0    = (const float*)d_in[1];
    const float* bn0_s = (const float*)d_in[2];
    const float* bn0_b = (const float*)d_in[3];
    const float* W1    = (const float*)d_in[4];
    const float* bn1_s = (const float*)d_in[5];
    const float* bn1_b = (const float*)d_in[6];
    const float* Wc    = (const float*)d_in[7];
    const float* bnc_s = (const float*)d_in[8];
    const float* bnc_b = (const float*)d_in[9];
    float* outp = (float*)d_out;

    cudaFuncSetAttribute(knn_kernel,
                         cudaFuncAttributeMaxDynamicSharedMemorySize, KNN_SMEM_BYTES);
    cudaFuncSetAttribute(edge_kernel,
                         cudaFuncAttributeMaxDynamicSharedMemorySize, SMEM_BYTES);

    knn_kernel<<<NPOINTS / KNN_PPB, KNN_THR, KNN_SMEM_BYTES>>>(x);
    edge_kernel<<<EDGE_GRID, THR, SMEM_BYTES>>>(
        x, W0, bn0_s, bn0_b, W1, bn1_s, bn1_b, Wc, bnc_s, bnc_b, outp);
}

// round 16
// speedup vs baseline: 1.8096x; 1.8096x over previous
#include <cuda_runtime.h>
#include <math.h>
#include <stdint.h>

#define NEG_SLOPE 0.2f
#define KNN_K 20
#define BATCH 8
#define NPTS 2048
#define CO 64
#define CIN 6
#define ROWS 384
#define NPOINTS (BATCH * NPTS)

__device__ int g_knn[NPOINTS * KNN_K];

typedef unsigned long long u64;

__device__ __forceinline__ void ffma2(u64& d, u64 a, u64 b) {
    asm("fma.rn.f32x2 %0, %1, %2, %0;" : "+l"(d) : "l"(a), "l"(b));
}
__device__ __forceinline__ u64 dup2(float w) {
    u64 r; asm("mov.b64 %0, {%1, %1};" : "=l"(r) : "f"(w)); return r;
}
__device__ __forceinline__ u64 pack2(float lo, float hi) {
    u64 r; asm("mov.b64 %0, {%1, %2};" : "=l"(r) : "f"(lo), "f"(hi)); return r;
}
__device__ __forceinline__ void unpack2(float& lo, float& hi, u64 v) {
    asm("mov.b64 {%0, %1}, %2;" : "=f"(lo), "=f"(hi) : "l"(v));
}

// ===========================================================================
// Kernel 1: KNN v3 — two-phase top-3 threshold.
// 256 blocks x 512 threads; 64 points/block, 8 segment-threads/point (256 j).
// Phase A: FULL scan, exact per-lane top-3 (cheap chain).  tau = min over the
// 8 lane-3rds — valid lower bound on the true 20th (pigeonhole: 8*3=24>20).
// Phase B: rescan collect d >= tau (exp ~40, cap 96).  Exact top-20 by
// (d desc, j asc) rank-select.  Overflow -> exact serial fallback.
// ===========================================================================
#define KNN_THR 512
#define KNN_PPB 64
#define KSEG 8
#define SEGLEN (NPTS / KSEG)          // 256
#define CAND_CAP 96

#define KOFF_P     0                                      // float4[2048] = 8192
#define KOFF_TH    (NPTS * 4)                             // [64][8] = 512
#define KOFF_TAU   (KOFF_TH + KNN_PPB * KSEG)             // 64
#define KOFF_CNT   (KOFF_TAU + KNN_PPB)                   // 64 (int)
#define KOFF_FLG   (KOFF_CNT + KNN_PPB)                   // 64 (int)
#define KOFF_CD    (KOFF_FLG + KNN_PPB)                   // [64][96]
#define KOFF_CJ    (KOFF_CD + KNN_PPB * CAND_CAP)         // [64][96] (int)
#define KNN_SMEM_FLOATS (KOFF_CJ + KNN_PPB * CAND_CAP)
#define KNN_SMEM_BYTES (KNN_SMEM_FLOATS * 4)

__global__ __launch_bounds__(KNN_THR) void knn_kernel(const float* __restrict__ x) {
    extern __shared__ float ksm[];
    float4* sP   = (float4*)(ksm + KOFF_P);
    float*  sTh  = ksm + KOFF_TH;
    float*  sTau = ksm + KOFF_TAU;
    int*    sCnt = (int*)(ksm + KOFF_CNT);
    int*    sFlg = (int*)(ksm + KOFF_FLG);
    float*  sCd  = ksm + KOFF_CD;
    int*    sCj  = (int*)(ksm + KOFF_CJ);

    const int b = blockIdx.x >> 5;
    const int chunk = blockIdx.x & 31;
    const float* xb = x + (size_t)b * 3 * NPTS;

    const int t = threadIdx.x;
    for (int j = t; j < NPTS; j += KNN_THR) {
        float a0 = xb[j], a1 = xb[NPTS + j], a2 = xb[2 * NPTS + j];
        float xx = (a0 * a0 + a1 * a1) + a2 * a2;
        sP[j] = make_float4(a0, a1, a2, xx);
    }
    if (t < KNN_PPB) { sCnt[t] = 0; sFlg[t] = 0; }
    __syncthreads();

    const int s  = t >> 6;        // segment 0..7 (warp-uniform)
    const int pp = t & 63;        // point within block
    const int i  = (chunk << 6) + pp;

    float4 cv = sP[i];
    const float c0 = cv.x, c1 = cv.y, c2 = cv.z, cxx = cv.w;
    const int j0 = s * SEGLEN;

    // ---- Phase A: exact per-lane top-3 over the FULL segment ----
    float t0 = -INFINITY, t1 = -INFINITY, t2 = -INFINITY;
#pragma unroll 4
    for (int jj = 0; jj < SEGLEN; jj++) {
        int j = j0 + jj;
        float4 p4 = sP[j];
        float d = c0 * p4.x;
        d = fmaf(c1, p4.y, d);
        d = fmaf(c2, p4.z, d);
        d = 2.0f * d - cxx - p4.w;
        if (d > t2) {
            float m0 = fmaxf(t0, d); d = fminf(t0, d); t0 = m0;
            float m1 = fmaxf(t1, d); d = fminf(t1, d); t1 = m1;
            t2 = fmaxf(t2, d);
        }
    }
    sTh[pp * 8 + s] = t2;
    __syncthreads();

    // ---- tau = min over lane-3rds (exact, once) ----
    if (t < KNN_PPB) {
        float m = sTh[t * 8];
#pragma unroll
        for (int q = 1; q < 8; q++) m = fminf(m, sTh[t * 8 + q]);
        sTau[t] = m;
    }
    __syncthreads();

    // ---- Phase B: rescan, collect d >= tau ----
    {
        const float tau = sTau[pp];
#pragma unroll 4
        for (int jj = 0; jj < SEGLEN; jj++) {
            int j = j0 + jj;
            float4 p4 = sP[j];
            float d = c0 * p4.x;
            d = fmaf(c1, p4.y, d);
            d = fmaf(c2, p4.z, d);
            d = 2.0f * d - cxx - p4.w;
            if (d >= tau) {
                int pos = atomicAdd(&sCnt[pp], 1);
                if (pos < CAND_CAP) {
                    sCd[pp * CAND_CAP + pos] = d;
                    sCj[pp * CAND_CAP + pos] = j;
                } else sFlg[pp] = 1;
            }
        }
    }
    __syncthreads();

    // ---- rank-based exact selection: top-20 by (d desc, j asc) ----
    for (int v2 = t; v2 < KNN_PPB * CAND_CAP; v2 += KNN_THR) {
        int pq = v2 / CAND_CAP;
        int q  = v2 - pq * CAND_CAP;
        if (sFlg[pq]) continue;
        int cnt = sCnt[pq];
        if (cnt > CAND_CAP) cnt = CAND_CAP;
        if (q < cnt) {
            const float* cd = sCd + pq * CAND_CAP;
            const int*   cj = sCj + pq * CAND_CAP;
            float d = cd[q]; int j = cj[q];
            int rank = 0;
            for (int q2 = 0; q2 < cnt; q2++) {
                float d2 = cd[q2]; int j2 = cj[q2];
                rank += ((d2 > d) || (d2 == d && j2 < j)) ? 1 : 0;
            }
            if (rank < KNN_K) {
                g_knn[((size_t)b * NPTS + (chunk << 6) + pq) * KNN_K + rank] = j;
            }
        }
    }

    // ---- overflow fallback (expected unreachable): exact serial per point
    if (s == 0 && sFlg[pp]) {
        float bd[KNN_K]; int bi[KNN_K];
#pragma unroll
        for (int k = 0; k < KNN_K; k++) { bd[k] = -INFINITY; bi[k] = 0; }
        for (int j = 0; j < NPTS; j++) {
            float4 p4 = sP[j];
            float d = c0 * p4.x;
            d = fmaf(c1, p4.y, d);
            d = fmaf(c2, p4.z, d);
            d = 2.0f * d - cxx - p4.w;
            if (d > bd[KNN_K - 1]) {
                float cdv = d; int civ = j;
#pragma unroll
                for (int k = 0; k < KNN_K; k++) {
                    bool sw = cdv > bd[k];
                    float td = bd[k]; int ti = bi[k];
                    if (sw) { bd[k] = cdv; bi[k] = civ; cdv = td; civ = ti; }
                }
            }
        }
        int* outp20 = g_knn + ((size_t)b * NPTS + i) * KNN_K;
#pragma unroll
        for (int k = 0; k < KNN_K; k++) outp20[k] = bi[k];
    }
}

// ===========================================================================
// Kernel 2: PERSISTENT fused edge kernel (148 blocks x 512 threads, PTS=8).
// (unchanged from R14 — whole-k single p-pass, 40 u64 G-accumulators)
// ===========================================================================
#define PTS 8
#define THR 512
#define NTILES ((NPOINTS + PTS - 1) / PTS)   // 2048
#define EDGE_GRID 148

#define EPAD 9
#define YROW 24

#define F_WQ   0
#define F_WB   (F_WQ + 16384)
#define F_Y    (F_WB + 8192)
#define F_E    (F_Y + 12288)
#define F_W0   (F_E + 1440)
#define F_B0S  (F_W0 + 384)
#define F_B0B  (F_B0S + 64)
#define F_B1S  (F_B0B + 64)
#define F_B1B  (F_B1S + 64)
#define F_WC   (F_B1B + 64)
#define F_BNC  (F_WC + 192)
#define F_X1   (F_BNC + 8)
#define SMEM_FLOATS (F_X1 + 512)
#define SMEM_BYTES (SMEM_FLOATS * 4)

__global__ __launch_bounds__(THR, 1) void edge_kernel(
    const float* __restrict__ x,
    const float* __restrict__ W0,
    const float* __restrict__ bn0_s, const float* __restrict__ bn0_b,
    const float* __restrict__ W1,
    const float* __restrict__ bn1_s, const float* __restrict__ bn1_b,
    const float* __restrict__ Wc,
    const float* __restrict__ bnc_s, const float* __restrict__ bnc_b,
    float* __restrict__ outp)
{
    extern __shared__ float sm[];
    float* sWq  = sm + F_WQ;
    float* sWb  = sm + F_WB;
    float* sY   = sm + F_Y;
    float* sE   = sm + F_E;
    float* sW0  = sm + F_W0;
    float* sB0s = sm + F_B0S;
    float* sB0b = sm + F_B0B;
    float* sB1s = sm + F_B1S;
    float* sB1b = sm + F_B1B;
    float* sWc  = sm + F_WC;
    float* sBnc = sm + F_BNC;
    float* sX1  = sm + F_X1;

    const int t = threadIdx.x;

    for (int g = t; g < ROWS * CO; g += THR) {
        int q = g >> 6;
        int p = g & 63;
        int oo = q / 6;
        int ii = q - oo * 6;
        float w = W1[g];
        if (ii < 4)       sWq[(p * 64 + oo) * 4 + ii] = w;
        else              sWb[(p * 64 + oo) * 2 + (ii - 4)] = w;
    }
    if (t < 384) sW0[t] = W0[t];
    if (t < 64) {
        sB0s[t] = bn0_s[t]; sB0b[t] = bn0_b[t];
        sB1s[t] = bn1_s[t]; sB1b[t] = bn1_b[t];
    }
    if (t < 192) sWc[t] = Wc[t];
    if (t < 3) { sBnc[t] = bnc_s[t]; sBnc[4 + t] = bnc_b[t]; }

    const int pt_g = t >> 6;
    const int o    = t & 63;

    for (int tile = blockIdx.x; tile < NTILES; tile += EDGE_GRID) {
        __syncthreads();

        if (t < PTS * KNN_K) {
            int pt = t / KNN_K, k = t - pt * KNN_K;
            int gp = tile * PTS + pt;
            float e0 = 0.f, e1 = 0.f, e2 = 0.f, c0 = 0.f, c1 = 0.f, c2 = 0.f;
            if (gp < NPOINTS) {
                int b = gp >> 11, n = gp & (NPTS - 1);
                const float* xb = x + (size_t)b * 3 * NPTS;
                c0 = xb[n]; c1 = xb[NPTS + n]; c2 = xb[2 * NPTS + n];
                int j = g_knn[((size_t)b * NPTS + n) * KNN_K + k];
                e0 = xb[j] - c0;
                e1 = xb[NPTS + j] - c1;
                e2 = xb[2 * NPTS + j] - c2;
            }
            float* e = sE + t * EPAD;
            e[0] = e0; e[1] = e1; e[2] = e2;
            e[3] = c0; e[4] = c1; e[5] = c2;
        }
        __syncthreads();

        for (int v = t; v < PTS * CO * KNN_K; v += THR) {
            int pt = v / (CO * KNN_K);
            int rem = v - pt * (CO * KNN_K);
            int p = rem / KNN_K;
            int k = rem - p * KNN_K;
            const float* e = sE + (pt * KNN_K + k) * EPAD;
            const float* w = sW0 + p * 6;
            float d = e[0] * w[0];
            d = fmaf(e[1], w[1], d);
            d = fmaf(e[2], w[2], d);
            d = fmaf(e[3], w[3], d);
            d = fmaf(e[4], w[4], d);
            d = fmaf(e[5], w[5], d);
            float yv = fmaf(d, sB0s[p], sB0b[p]);
            yv = (yv >= 0.0f) ? yv : NEG_SLOPE * yv;
            int half = k / 10, kk = k - half * 10;
            sY[(pt * CO + p) * YROW + half * 12 + kk] = yv;
        }
        __syncthreads();

        {
            const float* ept = sE + (pt_g * KNN_K) * EPAD;
            const float cc0 = ept[3], cc1 = ept[4], cc2 = ept[5];

            union F4 { float4 v; u64 d[2]; };

            u64 g0[10], g1[10], g2[10], gq[10];
#pragma unroll
            for (int q = 0; q < 10; q++) { g0[q] = 0; g1[q] = 0; g2[q] = 0; gq[q] = 0; }

            const float* yb = sY + (pt_g * CO) * YROW;

#pragma unroll 1
            for (int p = 0; p < CO; p++) {
                float4 wq = *(const float4*)(sWq + (p * 64 + o) * 4);
                float2 wb = *(const float2*)(sWb + (p * 64 + o) * 2);
                float qv = wq.w * cc0;
                qv = fmaf(wb.x, cc1, qv);
                qv = fmaf(wb.y, cc2, qv);
                u64 a0d = dup2(wq.x), a1d = dup2(wq.y), a2d = dup2(wq.z), qd = dup2(qv);

                const float* yrow = yb + p * YROW;
                F4 h0a, h0b, h1a, h1b;
                h0a.v = *(const float4*)(yrow);
                h0b.v = *(const float4*)(yrow + 4);
                u64 y4 = *(const u64*)(yrow + 8);
                h1a.v = *(const float4*)(yrow + 12);
                h1b.v = *(const float4*)(yrow + 16);
                u64 y9 = *(const u64*)(yrow + 20);

                u64 y[10];
                y[0] = h0a.d[0]; y[1] = h0a.d[1]; y[2] = h0b.d[0]; y[3] = h0b.d[1]; y[4] = y4;
                y[5] = h1a.d[0]; y[6] = h1a.d[1]; y[7] = h1b.d[0]; y[8] = h1b.d[1]; y[9] = y9;

#pragma unroll
                for (int q = 0; q < 10; q++) {
                    ffma2(g0[q], y[q], a0d);
                    ffma2(g1[q], y[q], a1d);
                    ffma2(g2[q], y[q], a2d);
                    ffma2(gq[q], y[q], qd);
                }
            }

            float maxv = -INFINITY;
#pragma unroll
            for (int q = 0; q < 10; q++) {
                const float* r0 = ept + (2 * q) * EPAD;
                const float* r1 = r0 + EPAD;
                u64 d0 = pack2(r0[0], r1[0]);
                u64 d1 = pack2(r0[1], r1[1]);
                u64 d2 = pack2(r0[2], r1[2]);
                u64 acc = gq[q];
                ffma2(acc, d0, g0[q]);
                ffma2(acc, d1, g1[q]);
                ffma2(acc, d2, g2[q]);
                float lo, hi;
                unpack2(lo, hi, acc);
                maxv = fmaxf(maxv, lo);
                maxv = fmaxf(maxv, hi);
            }

            float vv = fmaf(maxv, sB1s[o], sB1b[o]);
            vv = (vv >= 0.0f) ? vv : NEG_SLOPE * vv;
            sX1[pt_g * 64 + o] = vv;
        }
        __syncthreads();

        if (t < PTS * 3) {
            int pt = t / 3, c = t - pt * 3;
            int gp = tile * PTS + pt;
            if (gp < NPOINTS) {
                int b = gp >> 11, n = gp & (NPTS - 1);
                const float* x1 = sX1 + pt * 64;
                const float* w = sWc + c * 64;
                float d = 0.0f;
#pragma unroll
                for (int oo = 0; oo < 64; oo++) d = fmaf(x1[oo], w[oo], d);
                float z = fmaf(d, sBnc[c], sBnc[4 + c]);
                z = (z >= 0.0f) ? z : NEG_SLOPE * z;
                outp[((size_t)b * 3 + c) * NPTS + n] = z;
            }
        }
    }
}

// ---------------------------------------------------------------------------
extern "C" void kernel_launch(void* const* d_in, const int* in_sizes, int n_in,
                              void* d_out, int out_size)
{
    const float* x     = (const float*)d_in[0];
    const float* W0    = (const float*)d_in[1];
    const float* bn0_s = (const float*)d_in[2];
    const float* bn0_b = (const float*)d_in[3];
    const float* W1    = (const float*)d_in[4];
    const float* bn1_s = (const float*)d_in[5];
    const float* bn1_b = (const float*)d_in[6];
    const float* Wc    = (const float*)d_in[7];
    const float* bnc_s = (const float*)d_in[8];
    const float* bnc_b = (const float*)d_in[9];
    float* outp = (float*)d_out;

    cudaFuncSetAttribute(knn_kernel,
                         cudaFuncAttributeMaxDynamicSharedMemorySize, KNN_SMEM_BYTES);
    cudaFuncSetAttribute(edge_kernel,
                         cudaFuncAttributeMaxDynamicSharedMemorySize, SMEM_BYTES);

    knn_kernel<<<NPOINTS / KNN_PPB, KNN_THR, KNN_SMEM_BYTES>>>(x);
    edge_kernel<<<EDGE_GRID, THR, SMEM_BYTES>>>(
        x, W0, bn0_s, bn0_b, W1, bn1_s, bn1_b, Wc, bnc_s, bnc_b, outp);
}

// round 17
// speedup vs baseline: 2.8108x; 1.5533x over previous
#include <cuda_runtime.h>
#include <math.h>
#include <stdint.h>

#define NEG_SLOPE 0.2f
#define KNN_K 20
#define BATCH 8
#define NPTS 2048
#define CO 64
#define CIN 6
#define ROWS 384
#define NPOINTS (BATCH * NPTS)

__device__ int g_knn[NPOINTS * KNN_K];

typedef unsigned long long u64;

__device__ __forceinline__ void ffma2(u64& d, u64 a, u64 b) {
    asm("fma.rn.f32x2 %0, %1, %2, %0;" : "+l"(d) : "l"(a), "l"(b));
}
__device__ __forceinline__ u64 dup2(float w) {
    u64 r; asm("mov.b64 %0, {%1, %1};" : "=l"(r) : "f"(w)); return r;
}
__device__ __forceinline__ u64 pack2(float lo, float hi) {
    u64 r; asm("mov.b64 %0, {%1, %2};" : "=l"(r) : "f"(lo), "f"(hi)); return r;
}
__device__ __forceinline__ void unpack2(float& lo, float& hi, u64 v) {
    asm("mov.b64 {%0, %1}, %2;" : "=f"(lo), "=f"(hi) : "l"(v));
}

// ===========================================================================
// Kernel 1: KNN v4 — two-phase, tau = 20th largest of the UNION of per-lane
// top-3s (24 values; subset => its 20th <= true 20th => valid lower bound,
// and tight: cnt ~ 24-35).
// 256 blocks x 512 threads; 64 points/block, 8 segment-threads/point (256 j).
// Phase A: full scan, exact per-lane top-3 -> sTh[pp][8][3].
// tau: per point, 5th SMALLEST of the 24 (bottom-5 chain).
// Phase B: rescan collect d >= tau (cap 64).  Exact top-20 by (d desc, j asc)
// rank-select.  Overflow -> exact serial fallback (unreachable in practice).
// ===========================================================================
#define KNN_THR 512
#define KNN_PPB 64
#define KSEG 8
#define SEGLEN (NPTS / KSEG)          // 256
#define CAND_CAP 64

#define KOFF_P     0                                      // float4[2048] = 8192
#define KOFF_TH    (NPTS * 4)                             // [64][8][3] = 1536
#define KOFF_TAU   (KOFF_TH + KNN_PPB * KSEG * 3)         // 64
#define KOFF_CNT   (KOFF_TAU + KNN_PPB)                   // 64 (int)
#define KOFF_FLG   (KOFF_CNT + KNN_PPB)                   // 64 (int)
#define KOFF_CD    (KOFF_FLG + KNN_PPB)                   // [64][64]
#define KOFF_CJ    (KOFF_CD + KNN_PPB * CAND_CAP)         // [64][64] (int)
#define KNN_SMEM_FLOATS (KOFF_CJ + KNN_PPB * CAND_CAP)
#define KNN_SMEM_BYTES (KNN_SMEM_FLOATS * 4)

__global__ __launch_bounds__(KNN_THR) void knn_kernel(const float* __restrict__ x) {
    extern __shared__ float ksm[];
    float4* sP   = (float4*)(ksm + KOFF_P);
    float*  sTh  = ksm + KOFF_TH;
    float*  sTau = ksm + KOFF_TAU;
    int*    sCnt = (int*)(ksm + KOFF_CNT);
    int*    sFlg = (int*)(ksm + KOFF_FLG);
    float*  sCd  = ksm + KOFF_CD;
    int*    sCj  = (int*)(ksm + KOFF_CJ);

    const int b = blockIdx.x >> 5;
    const int chunk = blockIdx.x & 31;
    const float* xb = x + (size_t)b * 3 * NPTS;

    const int t = threadIdx.x;
    for (int j = t; j < NPTS; j += KNN_THR) {
        float a0 = xb[j], a1 = xb[NPTS + j], a2 = xb[2 * NPTS + j];
        float xx = (a0 * a0 + a1 * a1) + a2 * a2;
        sP[j] = make_float4(a0, a1, a2, xx);
    }
    if (t < KNN_PPB) { sCnt[t] = 0; sFlg[t] = 0; }
    __syncthreads();

    const int s  = t >> 6;        // segment 0..7 (warp-uniform)
    const int pp = t & 63;        // point within block
    const int i  = (chunk << 6) + pp;

    float4 cv = sP[i];
    const float c0 = cv.x, c1 = cv.y, c2 = cv.z, cxx = cv.w;
    const int j0 = s * SEGLEN;

    // ---- Phase A: exact per-lane top-3 over the full segment ----
    float t0 = -INFINITY, t1 = -INFINITY, t2 = -INFINITY;
#pragma unroll 4
    for (int jj = 0; jj < SEGLEN; jj++) {
        int j = j0 + jj;
        float4 p4 = sP[j];
        float d = c0 * p4.x;
        d = fmaf(c1, p4.y, d);
        d = fmaf(c2, p4.z, d);
        d = 2.0f * d - cxx - p4.w;
        if (d > t2) {
            float m0 = fmaxf(t0, d); d = fminf(t0, d); t0 = m0;
            float m1 = fmaxf(t1, d); d = fminf(t1, d); t1 = m1;
            t2 = fmaxf(t2, d);
        }
    }
    {
        float* th = sTh + (pp * 8 + s) * 3;
        th[0] = t0; th[1] = t1; th[2] = t2;
    }
    __syncthreads();

    // ---- tau = 20th largest of the 24 union values = 5th smallest ----
    if (t < KNN_PPB) {
        const float* th = sTh + t * 24;
        float b0 = INFINITY, b1 = INFINITY, b2 = INFINITY, b3 = INFINITY, b4 = INFINITY;
#pragma unroll 4
        for (int q = 0; q < 24; q++) {
            float d = th[q];
            if (d < b4) {
                float n0 = fminf(b0, d); d = fmaxf(b0, d); b0 = n0;
                float n1 = fminf(b1, d); d = fmaxf(b1, d); b1 = n1;
                float n2 = fminf(b2, d); d = fmaxf(b2, d); b2 = n2;
                float n3 = fminf(b3, d); d = fmaxf(b3, d); b3 = n3;
                b4 = fminf(b4, d);
            }
        }
        sTau[t] = b4;
    }
    __syncthreads();

    // ---- Phase B: rescan, collect d >= tau ----
    {
        const float tau = sTau[pp];
#pragma unroll 4
        for (int jj = 0; jj < SEGLEN; jj++) {
            int j = j0 + jj;
            float4 p4 = sP[j];
            float d = c0 * p4.x;
            d = fmaf(c1, p4.y, d);
            d = fmaf(c2, p4.z, d);
            d = 2.0f * d - cxx - p4.w;
            if (d >= tau) {
                int pos = atomicAdd(&sCnt[pp], 1);
                if (pos < CAND_CAP) {
                    sCd[pp * CAND_CAP + pos] = d;
                    sCj[pp * CAND_CAP + pos] = j;
                } else sFlg[pp] = 1;
            }
        }
    }
    __syncthreads();

    // ---- rank-based exact selection: top-20 by (d desc, j asc) ----
    for (int v2 = t; v2 < KNN_PPB * CAND_CAP; v2 += KNN_THR) {
        int pq = v2 >> 6;                 // / CAND_CAP
        int q  = v2 & (CAND_CAP - 1);
        if (sFlg[pq]) continue;
        int cnt = sCnt[pq];
        if (cnt > CAND_CAP) cnt = CAND_CAP;
        if (q < cnt) {
            const float* cd = sCd + pq * CAND_CAP;
            const int*   cj = sCj + pq * CAND_CAP;
            float d = cd[q]; int j = cj[q];
            int rank = 0;
            for (int q2 = 0; q2 < cnt; q2++) {
                float d2 = cd[q2]; int j2 = cj[q2];
                rank += ((d2 > d) || (d2 == d && j2 < j)) ? 1 : 0;
            }
            if (rank < KNN_K) {
                g_knn[((size_t)b * NPTS + (chunk << 6) + pq) * KNN_K + rank] = j;
            }
        }
    }

    // ---- overflow fallback (expected unreachable): exact serial per point
    if (s == 0 && sFlg[pp]) {
        float bd[KNN_K]; int bi[KNN_K];
#pragma unroll
        for (int k = 0; k < KNN_K; k++) { bd[k] = -INFINITY; bi[k] = 0; }
        for (int j = 0; j < NPTS; j++) {
            float4 p4 = sP[j];
            float d = c0 * p4.x;
            d = fmaf(c1, p4.y, d);
            d = fmaf(c2, p4.z, d);
            d = 2.0f * d - cxx - p4.w;
            if (d > bd[KNN_K - 1]) {
                float cdv = d; int civ = j;
#pragma unroll
                for (int k = 0; k < KNN_K; k++) {
                    bool sw = cdv > bd[k];
                    float td = bd[k]; int ti = bi[k];
                    if (sw) { bd[k] = cdv; bi[k] = civ; cdv = td; civ = ti; }
                }
            }
        }
        int* outp20 = g_knn + ((size_t)b * NPTS + i) * KNN_K;
#pragma unroll
        for (int k = 0; k < KNN_K; k++) outp20[k] = bi[k];
    }
}

// ===========================================================================
// Kernel 2: PERSISTENT fused edge kernel (148 blocks x 512 threads, PTS=8).
// (unchanged from R14 — whole-k single p-pass, 40 u64 G-accumulators)
// ===========================================================================
#define PTS 8
#define THR 512
#define NTILES ((NPOINTS + PTS - 1) / PTS)   // 2048
#define EDGE_GRID 148

#define EPAD 9
#define YROW 24

#define F_WQ   0
#define F_WB   (F_WQ + 16384)
#define F_Y    (F_WB + 8192)
#define F_E    (F_Y + 12288)
#define F_W0   (F_E + 1440)
#define F_B0S  (F_W0 + 384)
#define F_B0B  (F_B0S + 64)
#define F_B1S  (F_B0B + 64)
#define F_B1B  (F_B1S + 64)
#define F_WC   (F_B1B + 64)
#define F_BNC  (F_WC + 192)
#define F_X1   (F_BNC + 8)
#define SMEM_FLOATS (F_X1 + 512)
#define SMEM_BYTES (SMEM_FLOATS * 4)

__global__ __launch_bounds__(THR, 1) void edge_kernel(
    const float* __restrict__ x,
    const float* __restrict__ W0,
    const float* __restrict__ bn0_s, const float* __restrict__ bn0_b,
    const float* __restrict__ W1,
    const float* __restrict__ bn1_s, const float* __restrict__ bn1_b,
    const float* __restrict__ Wc,
    const float* __restrict__ bnc_s, const float* __restrict__ bnc_b,
    float* __restrict__ outp)
{
    extern __shared__ float sm[];
    float* sWq  = sm + F_WQ;
    float* sWb  = sm + F_WB;
    float* sY   = sm + F_Y;
    float* sE   = sm + F_E;
    float* sW0  = sm + F_W0;
    float* sB0s = sm + F_B0S;
    float* sB0b = sm + F_B0B;
    float* sB1s = sm + F_B1S;
    float* sB1b = sm + F_B1B;
    float* sWc  = sm + F_WC;
    float* sBnc = sm + F_BNC;
    float* sX1  = sm + F_X1;

    const int t = threadIdx.x;

    for (int g = t; g < ROWS * CO; g += THR) {
        int q = g >> 6;
        int p = g & 63;
        int oo = q / 6;
        int ii = q - oo * 6;
        float w = W1[g];
        if (ii < 4)       sWq[(p * 64 + oo) * 4 + ii] = w;
        else              sWb[(p * 64 + oo) * 2 + (ii - 4)] = w;
    }
    if (t < 384) sW0[t] = W0[t];
    if (t < 64) {
        sB0s[t] = bn0_s[t]; sB0b[t] = bn0_b[t];
        sB1s[t] = bn1_s[t]; sB1b[t] = bn1_b[t];
    }
    if (t < 192) sWc[t] = Wc[t];
    if (t < 3) { sBnc[t] = bnc_s[t]; sBnc[4 + t] = bnc_b[t]; }

    const int pt_g = t >> 6;
    const int o    = t & 63;

    for (int tile = blockIdx.x; tile < NTILES; tile += EDGE_GRID) {
        __syncthreads();

        if (t < PTS * KNN_K) {
            int pt = t / KNN_K, k = t - pt * KNN_K;
            int gp = tile * PTS + pt;
            float e0 = 0.f, e1 = 0.f, e2 = 0.f, c0 = 0.f, c1 = 0.f, c2 = 0.f;
            if (gp < NPOINTS) {
                int b = gp >> 11, n = gp & (NPTS - 1);
                const float* xb = x + (size_t)b * 3 * NPTS;
                c0 = xb[n]; c1 = xb[NPTS + n]; c2 = xb[2 * NPTS + n];
                int j = g_knn[((size_t)b * NPTS + n) * KNN_K + k];
                e0 = xb[j] - c0;
                e1 = xb[NPTS + j] - c1;
                e2 = xb[2 * NPTS + j] - c2;
            }
            float* e = sE + t * EPAD;
            e[0] = e0; e[1] = e1; e[2] = e2;
            e[3] = c0; e[4] = c1; e[5] = c2;
        }
        __syncthreads();

        for (int v = t; v < PTS * CO * KNN_K; v += THR) {
            int pt = v / (CO * KNN_K);
            int rem = v - pt * (CO * KNN_K);
            int p = rem / KNN_K;
            int k = rem - p * KNN_K;
            const float* e = sE + (pt * KNN_K + k) * EPAD;
            const float* w = sW0 + p * 6;
            float d = e[0] * w[0];
            d = fmaf(e[1], w[1], d);
            d = fmaf(e[2], w[2], d);
            d = fmaf(e[3], w[3], d);
            d = fmaf(e[4], w[4], d);
            d = fmaf(e[5], w[5], d);
            float yv = fmaf(d, sB0s[p], sB0b[p]);
            yv = (yv >= 0.0f) ? yv : NEG_SLOPE * yv;
            int half = k / 10, kk = k - half * 10;
            sY[(pt * CO + p) * YROW + half * 12 + kk] = yv;
        }
        __syncthreads();

        {
            const float* ept = sE + (pt_g * KNN_K) * EPAD;
            const float cc0 = ept[3], cc1 = ept[4], cc2 = ept[5];

            union F4 { float4 v; u64 d[2]; };

            u64 g0[10], g1[10], g2[10], gq[10];
#pragma unroll
            for (int q = 0; q < 10; q++) { g0[q] = 0; g1[q] = 0; g2[q] = 0; gq[q] = 0; }

            const float* yb = sY + (pt_g * CO) * YROW;

#pragma unroll 1
            for (int p = 0; p < CO; p++) {
                float4 wq = *(const float4*)(sWq + (p * 64 + o) * 4);
                float2 wb = *(const float2*)(sWb + (p * 64 + o) * 2);
                float qv = wq.w * cc0;
                qv = fmaf(wb.x, cc1, qv);
                qv = fmaf(wb.y, cc2, qv);
                u64 a0d = dup2(wq.x), a1d = dup2(wq.y), a2d = dup2(wq.z), qd = dup2(qv);

                const float* yrow = yb + p * YROW;
                F4 h0a, h0b, h1a, h1b;
                h0a.v = *(const float4*)(yrow);
                h0b.v = *(const float4*)(yrow + 4);
                u64 y4 = *(const u64*)(yrow + 8);
                h1a.v = *(const float4*)(yrow + 12);
                h1b.v = *(const float4*)(yrow + 16);
                u64 y9 = *(const u64*)(yrow + 20);

                u64 y[10];
                y[0] = h0a.d[0]; y[1] = h0a.d[1]; y[2] = h0b.d[0]; y[3] = h0b.d[1]; y[4] = y4;
                y[5] = h1a.d[0]; y[6] = h1a.d[1]; y[7] = h1b.d[0]; y[8] = h1b.d[1]; y[9] = y9;

#pragma unroll
                for (int q = 0; q < 10; q++) {
                    ffma2(g0[q], y[q], a0d);
                    ffma2(g1[q], y[q], a1d);
                    ffma2(g2[q], y[q], a2d);
                    ffma2(gq[q], y[q], qd);
                }
            }

            float maxv = -INFINITY;
#pragma unroll
            for (int q = 0; q < 10; q++) {
                const float* r0 = ept + (2 * q) * EPAD;
                const float* r1 = r0 + EPAD;
                u64 d0 = pack2(r0[0], r1[0]);
                u64 d1 = pack2(r0[1], r1[1]);
                u64 d2 = pack2(r0[2], r1[2]);
                u64 acc = gq[q];
                ffma2(acc, d0, g0[q]);
                ffma2(acc, d1, g1[q]);
                ffma2(acc, d2, g2[q]);
                float lo, hi;
                unpack2(lo, hi, acc);
                maxv = fmaxf(maxv, lo);
                maxv = fmaxf(maxv, hi);
            }

            float vv = fmaf(maxv, sB1s[o], sB1b[o]);
            vv = (vv >= 0.0f) ? vv : NEG_SLOPE * vv;
            sX1[pt_g * 64 + o] = vv;
        }
        __syncthreads();

        if (t < PTS * 3) {
            int pt = t / 3, c = t - pt * 3;
            int gp = tile * PTS + pt;
            if (gp < NPOINTS) {
                int b = gp >> 11, n = gp & (NPTS - 1);
                const float* x1 = sX1 + pt * 64;
                const float* w = sWc + c * 64;
                float d = 0.0f;
#pragma unroll
                for (int oo = 0; oo < 64; oo++) d = fmaf(x1[oo], w[oo], d);
                float z = fmaf(d, sBnc[c], sBnc[4 + c]);
                z = (z >= 0.0f) ? z : NEG_SLOPE * z;
                outp[((size_t)b * 3 + c) * NPTS + n] = z;
            }
        }
    }
}

// ---------------------------------------------------------------------------
extern "C" void kernel_launch(void* const* d_in, const int* in_sizes, int n_in,
                              void* d_out, int out_size)
{
    const float* x     = (const float*)d_in[0];
    const float* W0    = (const float*)d_in[1];
    const float* bn0_s = (const float*)d_in[2];
    const float* bn0_b = (const float*)d_in[3];
    const float* W1    = (const float*)d_in[4];
    const float* bn1_s = (const float*)d_in[5];
    const float* bn1_b = (const float*)d_in[6];
    const float* Wc    = (const float*)d_in[7];
    const float* bnc_s = (const float*)d_in[8];
    const float* bnc_b = (const float*)d_in[9];
    float* outp = (float*)d_out;

    cudaFuncSetAttribute(knn_kernel,
                         cudaFuncAttributeMaxDynamicSharedMemorySize, KNN_SMEM_BYTES);
    cudaFuncSetAttribute(edge_kernel,
                         cudaFuncAttributeMaxDynamicSharedMemorySize, SMEM_BYTES);

    knn_kernel<<<NPOINTS / KNN_PPB, KNN_THR, KNN_SMEM_BYTES>>>(x);
    edge_kernel<<<EDGE_GRID, THR, SMEM_BYTES>>>(
        x, W0, bn0_s, bn0_b, W1, bn1_s, bn1_b, Wc, bnc_s, bnc_b, outp);
}